// round 16
// baseline (speedup 1.0000x reference)
#include <cuda_runtime.h>
#include <math.h>

#define BATCH   128
#define DD      128
#define HH      256
#define NBLK_C  256
#define THREADS 1024
#define SEC     (BATCH*NBLK_C)

typedef unsigned long long u64;

// ---- device scratch ----
__device__ __align__(16) float g_E[BATCH * 511 * DD];
__device__ __align__(16) float g_BP[BATCH * 255 * HH];
__device__ int   g_X[BATCH * 511];
__device__ int   g_U1H[BATCH * 256];
__device__ int   g_fenc[BATCH * NBLK_C];
__device__ __align__(16) float g_Wf[256 * 512];    // [Wc1 | Wb1-top] col-fused (k-major)
__device__ __align__(16) float g_WfT[512 * 256];   // transposed: row = out col, contiguous k
__device__ __align__(16) float g_Wc2T[128 * 256];  // transposed Wc2
__device__ __align__(16) float g_Wb2T[128 * 256];  // transposed Wb2
__device__ __align__(16) float g_bf[512];          // [bc1 | bb1]
__device__ __align__(16) float g_emb[2 * HH];      // E_lab[u] @ Wb1[256:384,:]
__device__ __align__(16) float g_w2l[512];         // [Wc2@Wl | Wb2@Wl]
__device__ float g_pbias[2];

// ---- f32x2 helpers ----
__device__ __forceinline__ void fma2(u64& acc, u64 a, u64 b) {
    asm("fma.rn.f32x2 %0, %1, %2, %0;" : "+l"(acc) : "l"(a), "l"(b));
}
__device__ __forceinline__ u64 pk2(float x, float y) {
    u64 r; asm("mov.b64 %0, {%1, %2};" : "=l"(r) : "f"(x), "f"(y)); return r;
}
__device__ __forceinline__ float2 upk(u64 v) {
    float2 r; asm("mov.b64 {%0, %1}, %2;" : "=f"(r.x), "=f"(r.y) : "l"(v)); return r;
}

struct Ctx {
    float* Eb; float* BPb; int* Xb; int* U1Hb;
    float* sa;     // 32 KB: L1 input acts (big stages)
    float* hs;     // 32 KB: hidden
    float* arena;  // 64 KB: split-K partials (big stages)
    float* nbp; int* nx;
    const float* Wc2; const float* bc2;
    const float* Wb2; const float* bb2;
    const float* r_in;
    float* u_out; float* p_out;
    int b;
};

// ================= warp-local transposed GEMMs (small stages, R<=8) =================
// L1 fused: [R x 256] @ [256 x 512]; col<256 -> relu -> hs; col>=256 -> bp_out.
// One warp owns CPW=16R consecutive cols of one row. k split over 32 lanes; shfl reduce.
template<int R>
__device__ void l1_warpT(Ctx& c, const float* __restrict__ Ein, float* __restrict__ bp_out)
{
    const int t = threadIdx.x, w = t >> 5, lane = t & 31;
    constexpr int WPR = 32 / R;          // warps per row
    constexpr int CPW = 512 / WPR;       // cols per warp
    const int row  = w / WPR;
    const int col0 = (w % WPR) * CPW;
    const float* arow = Ein + row * 256 + lane * 8;
    float4 a0 = __ldg((const float4*)arow);
    float4 a1 = __ldg((const float4*)(arow + 4));
    u64 ap0 = pk2(a0.x, a0.y), ap1 = pk2(a0.z, a0.w);
    u64 ap2 = pk2(a1.x, a1.y), ap3 = pk2(a1.z, a1.w);
    #pragma unroll 4
    for (int cc = 0; cc < CPW; cc += 2) {
        const int colA = col0 + cc;
        const float4* WA = (const float4*)&g_WfT[(size_t)colA * 256 + lane * 8];
        const float4* WB = (const float4*)&g_WfT[(size_t)(colA + 1) * 256 + lane * 8];
        float4 wa0 = __ldg(WA), wa1 = __ldg(WA + 1);
        float4 wb0 = __ldg(WB), wb1 = __ldg(WB + 1);
        u64 sA = 0ull, sB = 0ull;
        fma2(sA, ap0, pk2(wa0.x, wa0.y)); fma2(sA, ap1, pk2(wa0.z, wa0.w));
        fma2(sA, ap2, pk2(wa1.x, wa1.y)); fma2(sA, ap3, pk2(wa1.z, wa1.w));
        fma2(sB, ap0, pk2(wb0.x, wb0.y)); fma2(sB, ap1, pk2(wb0.z, wb0.w));
        fma2(sB, ap2, pk2(wb1.x, wb1.y)); fma2(sB, ap3, pk2(wb1.z, wb1.w));
        float2 vA = upk(sA), vB = upk(sB);
        float fA = vA.x + vA.y, fB = vB.x + vB.y;
        #pragma unroll
        for (int o = 16; o > 0; o >>= 1) {
            fA += __shfl_xor_sync(0xffffffffu, fA, o);
            fB += __shfl_xor_sync(0xffffffffu, fB, o);
        }
        if (lane == 0) {
            float oA = fA + g_bf[colA], oB = fB + g_bf[colA + 1];
            if (colA < 256) {
                c.hs[row * 256 + colA]     = fmaxf(oA, 0.f);
                c.hs[row * 256 + colA + 1] = fmaxf(oB, 0.f);
            } else {
                bp_out[row * HH + colA - 256] = oA;
                bp_out[row * HH + colA - 255] = oB;
            }
        }
    }
    __syncthreads();
}

// L2: [R x 256] @ [256 x 128] + b2 -> Eout. BIT: act = relu(bp+emb[u]); publishes u1h.
template<int R, bool BIT>
__device__ void l2_warpT(Ctx& c, const float* __restrict__ W2T,
                         const float* __restrict__ b2, float* __restrict__ Eout,
                         const float* __restrict__ BPl, const int* __restrict__ Xlm,
                         int* __restrict__ u1h)
{
    const int t = threadIdx.x, w = t >> 5, lane = t & 31;
    constexpr int WPR = 32 / R;
    constexpr int CPW = 128 / WPR;       // = 4R
    const int row  = w / WPR;
    const int col0 = (w % WPR) * CPW;
    u64 ap0, ap1, ap2, ap3;
    if constexpr (!BIT) {
        const float* arow = c.hs + row * 256 + lane * 8;
        float4 a0 = *(const float4*)arow;
        float4 a1 = *(const float4*)(arow + 4);
        ap0 = pk2(a0.x, a0.y); ap1 = pk2(a0.z, a0.w);
        ap2 = pk2(a1.x, a1.y); ap3 = pk2(a1.z, a1.w);
    } else {
        const int u = Xlm[row];
        if ((w % WPR) == 0 && lane == 0) u1h[row] = u;
        const float* bprow = BPl + (size_t)row * HH + lane * 8;
        float4 b0 = __ldg((const float4*)bprow);
        float4 b1 = __ldg((const float4*)(bprow + 4));
        const float* erow = g_emb + u * HH + lane * 8;
        float4 e0 = __ldg((const float4*)erow);
        float4 e1 = __ldg((const float4*)(erow + 4));
        ap0 = pk2(fmaxf(b0.x + e0.x, 0.f), fmaxf(b0.y + e0.y, 0.f));
        ap1 = pk2(fmaxf(b0.z + e0.z, 0.f), fmaxf(b0.w + e0.w, 0.f));
        ap2 = pk2(fmaxf(b1.x + e1.x, 0.f), fmaxf(b1.y + e1.y, 0.f));
        ap3 = pk2(fmaxf(b1.z + e1.z, 0.f), fmaxf(b1.w + e1.w, 0.f));
    }
    #pragma unroll 4
    for (int cc = 0; cc < CPW; cc += 2) {
        const int colA = col0 + cc;
        const float4* WA = (const float4*)&W2T[(size_t)colA * 256 + lane * 8];
        const float4* WB = (const float4*)&W2T[(size_t)(colA + 1) * 256 + lane * 8];
        float4 wa0 = __ldg(WA), wa1 = __ldg(WA + 1);
        float4 wb0 = __ldg(WB), wb1 = __ldg(WB + 1);
        u64 sA = 0ull, sB = 0ull;
        fma2(sA, ap0, pk2(wa0.x, wa0.y)); fma2(sA, ap1, pk2(wa0.z, wa0.w));
        fma2(sA, ap2, pk2(wa1.x, wa1.y)); fma2(sA, ap3, pk2(wa1.z, wa1.w));
        fma2(sB, ap0, pk2(wb0.x, wb0.y)); fma2(sB, ap1, pk2(wb0.z, wb0.w));
        fma2(sB, ap2, pk2(wb1.x, wb1.y)); fma2(sB, ap3, pk2(wb1.z, wb1.w));
        float2 vA = upk(sA), vB = upk(sB);
        float fA = vA.x + vA.y, fB = vB.x + vB.y;
        #pragma unroll
        for (int o = 16; o > 0; o >>= 1) {
            fA += __shfl_xor_sync(0xffffffffu, fA, o);
            fB += __shfl_xor_sync(0xffffffffu, fB, o);
        }
        if (lane == 0) {
            Eout[row * 128 + colA]     = fA + __ldg(&b2[colA]);
            Eout[row * 128 + colA + 1] = fB + __ldg(&b2[colA + 1]);
        }
    }
    __syncthreads();
}

// ================= block split-K GEMMs (big stages, R>=16) — R12-identical =================
template<int R, int RG, int KP>
__device__ void l1_gemm(Ctx& c, const float* __restrict__ Ein, float* __restrict__ bp_out)
{
    const int t = threadIdx.x;
    constexpr int NR = R / RG;
    constexpr int KL = 256 / KP;
    {
        const float4* src = (const float4*)Ein;
        float4* dst = (float4*)c.sa;
        for (int i = t; i < R * 64; i += THREADS) dst[i] = src[i];
    }
    __syncthreads();
    const int colq = t & 127;
    const int s  = t >> 7;
    const int rg = s % RG;
    const int kp = s / RG;
    const int k0 = kp * KL;
    const int r0 = rg * NR;
    u64 acc[NR][2];
    #pragma unroll
    for (int j = 0; j < NR; j++) { acc[j][0] = 0ull; acc[j][1] = 0ull; }
    const ulonglong2* W = (const ulonglong2*)g_Wf + colq;
    #pragma unroll 2
    for (int k = k0; k < k0 + KL; k += 2) {
        ulonglong2 w0 = __ldg(W + (size_t)k * 128);
        ulonglong2 w1 = __ldg(W + (size_t)(k + 1) * 128);
        #pragma unroll
        for (int j = 0; j < NR; j++) {
            float2 a = *((const float2*)&c.sa[(r0 + j) * 256 + k]);
            u64 ax = pk2(a.x, a.x), ay = pk2(a.y, a.y);
            fma2(acc[j][0], ax, w0.x); fma2(acc[j][1], ax, w0.y);
            fma2(acc[j][0], ay, w1.x); fma2(acc[j][1], ay, w1.y);
        }
    }
    if constexpr (KP == 1) {
        const int col = colq * 4;
        float4 bias = *((const float4*)&g_bf[col]);
        #pragma unroll
        for (int j = 0; j < NR; j++) {
            int row = r0 + j;
            float2 v0 = upk(acc[j][0]); float2 v1 = upk(acc[j][1]);
            float o0 = v0.x + bias.x, o1 = v0.y + bias.y;
            float o2 = v1.x + bias.z, o3 = v1.y + bias.w;
            if (col < 256)
                *((float4*)&c.hs[row * 256 + col]) =
                    make_float4(fmaxf(o0,0.f), fmaxf(o1,0.f), fmaxf(o2,0.f), fmaxf(o3,0.f));
            else
                *((float4*)&bp_out[row * HH + (col - 256)]) = make_float4(o0, o1, o2, o3);
        }
        __syncthreads();
    } else {
        ulonglong2* ar = (ulonglong2*)c.arena;
        #pragma unroll
        for (int j = 0; j < NR; j++) {
            ulonglong2 v; v.x = acc[j][0]; v.y = acc[j][1];
            ar[(s * NR + j) * 128 + colq] = v;
        }
        __syncthreads();
        for (int o = t; o < R * 128; o += THREADS) {
            int row = o >> 7, cq = o & 127;
            int jr = row % NR, rr = row / NR;
            float sx = 0.f, sy = 0.f, sz = 0.f, sw = 0.f;
            #pragma unroll
            for (int q = 0; q < KP; q++) {
                ulonglong2 v = ar[((q * RG + rr) * NR + jr) * 128 + cq];
                float2 p0 = upk(v.x), p1 = upk(v.y);
                sx += p0.x; sy += p0.y; sz += p1.x; sw += p1.y;
            }
            int col = cq * 4;
            float4 bias = *((const float4*)&g_bf[col]);
            sx += bias.x; sy += bias.y; sz += bias.z; sw += bias.w;
            if (col < 256)
                *((float4*)&c.hs[row * 256 + col]) =
                    make_float4(fmaxf(sx,0.f), fmaxf(sy,0.f), fmaxf(sz,0.f), fmaxf(sw,0.f));
            else
                *((float4*)&bp_out[row * HH + (col - 256)]) = make_float4(sx, sy, sz, sw);
        }
        __syncthreads();
    }
}

template<int R, int RG, int KP>
__device__ void l2_gemm(Ctx& c, const float* __restrict__ W2,
                        const float* __restrict__ b2, float* __restrict__ Eout)
{
    const int t = threadIdx.x;
    constexpr int NR = R / RG;
    constexpr int KL = 256 / KP;
    const int colq = t & 31;
    const int s  = t >> 5;
    const int rg = s % RG;
    const int kp = s / RG;
    const int k0 = kp * KL;
    const int r0 = rg * NR;
    u64 acc[NR][2];
    #pragma unroll
    for (int j = 0; j < NR; j++) { acc[j][0] = 0ull; acc[j][1] = 0ull; }
    const ulonglong2* W = (const ulonglong2*)W2 + colq;
    #pragma unroll 2
    for (int k = k0; k < k0 + KL; k += 2) {
        ulonglong2 w0 = __ldg(W + (size_t)k * 32);
        ulonglong2 w1 = __ldg(W + (size_t)(k + 1) * 32);
        #pragma unroll
        for (int j = 0; j < NR; j++) {
            float2 a = *((const float2*)&c.hs[(r0 + j) * 256 + k]);
            u64 ax = pk2(a.x, a.x), ay = pk2(a.y, a.y);
            fma2(acc[j][0], ax, w0.x); fma2(acc[j][1], ax, w0.y);
            fma2(acc[j][0], ay, w1.x); fma2(acc[j][1], ay, w1.y);
        }
    }
    ulonglong2* ar = (ulonglong2*)c.arena;
    #pragma unroll
    for (int j = 0; j < NR; j++) {
        ulonglong2 v; v.x = acc[j][0]; v.y = acc[j][1];
        ar[(s * NR + j) * 32 + colq] = v;
    }
    __syncthreads();
    for (int o = t; o < R * 32; o += THREADS) {
        int row = o >> 5, cq = o & 31;
        int jr = row % NR, rr = row / NR;
        float sx = 0.f, sy = 0.f, sz = 0.f, sw = 0.f;
        #pragma unroll
        for (int q = 0; q < KP; q++) {
            ulonglong2 v = ar[((q * RG + rr) * NR + jr) * 32 + cq];
            float2 p0 = upk(v.x), p1 = upk(v.y);
            sx += p0.x; sy += p0.y; sz += p1.x; sw += p1.y;
        }
        int col = cq * 4;
        float4 bb = *((const float4*)&b2[col]);
        *((float4*)&Eout[row * 128 + col]) =
            make_float4(sx + bb.x, sy + bb.y, sz + bb.z, sw + bb.w);
    }
    __syncthreads();
}

__device__ void check_stage(Ctx& c, int l)
{
    const int half = 1 << (l - 1);
    const float* Ein = c.Eb + ((1 << l) - 1) * DD;
    float* Eout = c.Eb + (half - 1) * DD;
    float* BPl  = c.BPb + (half - 1) * HH;
    if (half == 2)       { l1_warpT<2>(c, Ein, BPl); l2_warpT<2,false>(c, g_Wc2T, c.bc2, Eout, nullptr, nullptr, nullptr); }
    else if (half == 4)  { l1_warpT<4>(c, Ein, BPl); l2_warpT<4,false>(c, g_Wc2T, c.bc2, Eout, nullptr, nullptr, nullptr); }
    else if (half == 8)  { l1_warpT<8>(c, Ein, BPl); l2_warpT<8,false>(c, g_Wc2T, c.bc2, Eout, nullptr, nullptr, nullptr); }
    else if (half == 16) { l1_gemm<16,4,2>(c, Ein, BPl);  l2_gemm<16,4,8>(c, c.Wc2, c.bc2, Eout); }
    else {
        for (int done = 0; done < half; done += 32) {
            l1_gemm<32,8,1>(c, Ein + done * 256, BPl + done * HH);
            l2_gemm<32,8,4>(c, c.Wc2, c.bc2, Eout + done * DD);
        }
    }
}

__device__ void bit_hidden(Ctx& c, const float* BPl, const int* u1h, int done, int rbc)
{
    for (int idx = threadIdx.x; idx < rbc * 256; idx += THREADS) {
        int row = idx >> 8, k = idx & 255;
        int u = u1h[done + row];
        c.hs[idx] = fmaxf(BPl[(done + row) * HH + k] + g_emb[u * HH + k], 0.f);
    }
    __syncthreads();
}

__device__ void bit_stage(Ctx& c, int l)
{
    const int half = 1 << (l - 1);
    const int base = half - 1;
    float* Eout = c.Eb + base * DD;
    const float* BPl = c.BPb + base * HH;
    int* u1h = c.U1Hb + base;
    int* Xlm = c.Xb + base;
    if (half == 2)      { l2_warpT<2,true>(c, g_Wb2T, c.bb2, Eout, BPl, Xlm, u1h); return; }
    else if (half == 4) { l2_warpT<4,true>(c, g_Wb2T, c.bb2, Eout, BPl, Xlm, u1h); return; }
    else if (half == 8) { l2_warpT<8,true>(c, g_Wb2T, c.bb2, Eout, BPl, Xlm, u1h); return; }
    __syncthreads();
    for (int i = threadIdx.x; i < half; i += THREADS) u1h[i] = Xlm[i];
    __syncthreads();
    if (half == 16) { bit_hidden(c, BPl, u1h, 0, 16); l2_gemm<16,4,8>(c, c.Wb2, c.bb2, Eout); }
    else {
        for (int done = 0; done < half; done += 32) {
            bit_hidden(c, BPl, u1h, done, 32);
            l2_gemm<32,8,4>(c, c.Wb2, c.bb2, Eout + done * DD);
        }
    }
}

__device__ __forceinline__ void combine_stage(Ctx& c, int l)
{
    int half = 1 << (l - 1);
    int* u1h = c.U1Hb + (half - 1);
    int* Xlm = c.Xb + (half - 1);
    int* Xl  = c.Xb + ((1 << l) - 1);
    __syncthreads();
    for (int i = threadIdx.x; i < half; i += THREADS) {
        int u2 = Xlm[i];
        Xl[2 * i]     = u1h[i] ^ u2;
        Xl[2 * i + 1] = u2;
    }
    __syncthreads();
}

// Fused level-1 node: warp-T L1 + leaf dots vs precomputed W2@Wl
__device__ void node1(Ctx& c, int n)
{
    const int t = threadIdx.x;
    const float* Ein = c.Eb + DD;           // level-1 rows (256 floats)
    l1_warpT<1>(c, Ein, c.nbp);             // hidden -> c.hs[0..256), bp -> c.nbp
    if (t < 32) {
        float s = 0.f;
        #pragma unroll
        for (int j = 0; j < 8; j++) s = fmaf(c.hs[t + 32 * j], g_w2l[t + 32 * j], s);
        #pragma unroll
        for (int o = 16; o > 0; o >>= 1) s += __shfl_xor_sync(0xffffffffu, s, o);
        if (t == 0) {
            float p = 1.f / (1.f + expf(-(s + g_pbias[0])));
            int leaf = 2 * n;
            float rv = __ldg(&c.r_in[c.b * NBLK_C + leaf]);
            int f  = g_fenc[c.b * NBLK_C + leaf];
            int hd = (rv > p) ? 1 : 0;
            int x  = ((f == 2) || (fabsf(p - 0.5f) > 0.25f)) ? hd : f;
            *c.nx = x;
            c.u_out[c.b * NBLK_C + leaf] = (float)x;
            c.p_out[c.b * NBLK_C + leaf] = p;
        }
    }
    __syncthreads();
    int xL = *c.nx;
    if (t < 256)
        c.arena[t] = fmaxf(c.nbp[t] + g_emb[xL * HH + t], 0.f) * g_w2l[256 + t];
    __syncthreads();
    if (t < 32) {
        float s = 0.f;
        #pragma unroll
        for (int j = 0; j < 8; j++) s += c.arena[t + 32 * j];
        #pragma unroll
        for (int o = 16; o > 0; o >>= 1) s += __shfl_xor_sync(0xffffffffu, s, o);
        if (t == 0) {
            float p = 1.f / (1.f + expf(-(s + g_pbias[1])));
            int leaf = 2 * n + 1;
            float rv = __ldg(&c.r_in[c.b * NBLK_C + leaf]);
            int f  = g_fenc[c.b * NBLK_C + leaf];
            int hd = (rv > p) ? 1 : 0;
            int xR = ((f == 2) || (fabsf(p - 0.5f) > 0.25f)) ? hd : f;
            c.u_out[c.b * NBLK_C + leaf] = (float)xR;
            c.p_out[c.b * NBLK_C + leaf] = p;
            c.Xb[1] = xL ^ xR;   // combine(1)
            c.Xb[2] = xR;
        }
    }
    __syncthreads();
}

__global__ void __launch_bounds__(THREADS, 1)
sc_main(const float* r_in,
        const float* Wc2, const float* bc2,
        const float* Wb2, const float* bb2,
        float* out)
{
    extern __shared__ __align__(16) char smraw[];
    Ctx c;
    c.sa    = (float*)smraw;           // 32 KB
    c.hs    = c.sa + 8192;             // 32 KB
    c.arena = c.hs + 8192;             // 64 KB
    c.nbp   = c.arena + 16384;         // 1 KB
    c.nx    = (int*)(c.nbp + 256);
    c.b = blockIdx.x;
    c.Eb   = g_E   + (size_t)c.b * 511 * DD;
    c.BPb  = g_BP  + (size_t)c.b * 255 * HH;
    c.Xb   = g_X   + c.b * 511;
    c.U1Hb = g_U1H + c.b * 256;
    c.Wc2 = Wc2; c.bc2 = bc2; c.Wb2 = Wb2; c.bb2 = bb2;
    c.r_in  = r_in;
    c.u_out = out + 2 * SEC;
    c.p_out = out + 3 * SEC;

    for (int l = 8; l >= 2; l--) check_stage(c, l);
    for (int n = 0; n < 128; n++) {
        node1(c, n);
        if (n == 127) break;
        int l = 2;
        while ((n >> (l - 2)) & 1) { combine_stage(c, l); l++; }
        bit_stage(c, l);
        for (int ld = l - 1; ld >= 2; ld--) check_stage(c, ld);
    }
    for (int l = 2; l <= 8; l++) combine_stage(c, l);

    int* X8 = c.Xb + 255;
    for (int i = threadIdx.x; i < NBLK_C; i += THREADS)
        out[c.b * NBLK_C + i] = (float)X8[i];
}

// ---- merged init: setup (all blocks) + prep (blocks 0..63) + transposes (blocks 64..127) ----
__global__ void sc_init(const int* info_bits, const float* r_in, const int* info_set,
                        const float* E_obs, float* out,
                        const float* Wc1, const float* bc1,
                        const float* Wb1, const float* bb1,
                        const float* E_lab,
                        const float* Wc2, const float* bc2,
                        const float* Wb2, const float* bb2,
                        const float* Wl, const float* bl)
{
    int b = blockIdx.x, t = threadIdx.x;
    for (int j = t; j < NBLK_C; j += blockDim.x) {
        g_fenc[b * NBLK_C + j] = 2;
        out[1 * SEC + b * NBLK_C + j] = 1.0f;
        out[4 * SEC + b * NBLK_C + j] = r_in[b * NBLK_C + j];
    }
    __syncthreads();
    for (int k = t; k < 128; k += blockDim.x) {
        int pos = info_set[k];
        g_fenc[b * NBLK_C + pos] = info_bits[b * 128 + k];
        out[1 * SEC + b * NBLK_C + pos] = 2.0f;
    }
    for (int idx = t; idx < 256 * DD; idx += blockDim.x) {
        int i = idx >> 7, k = idx & (DD - 1);
        g_E[(size_t)b * 511 * DD + (255 + i) * DD + k] = E_obs[2 * DD + k];
    }
    if (b < 64) {
        int tid = b * 512 + t;
        {
            int k = tid >> 7, c4 = (tid & 127) * 4;
            float4 v;
            if (c4 < 256) v = *((const float4*)&Wc1[k * 256 + c4]);
            else          v = *((const float4*)&Wb1[k * 256 + (c4 - 256)]);
            *((float4*)&g_Wf[k * 512 + c4]) = v;
        }
        if (tid < 512) g_bf[tid] = (tid < 256) ? bc1[tid] : bb1[tid - 256];
        if (tid >= 512 && tid < 1024) {
            int cidx = tid - 512;
            const float* W2 = (cidx < 256) ? Wc2 : Wb2;
            int k = cidx & 255;
            float s = 0.f;
            for (int d = 0; d < 128; d++) s += W2[k * 128 + d] * Wl[d];
            g_w2l[cidx] = s;
        }
        if (tid >= 1024 && tid < 1536) {
            int cidx = tid - 1024; int u = cidx >> 8, j = cidx & 255;
            float s = 0.f;
            for (int d = 0; d < 128; d++) s += E_lab[u * 128 + d] * Wb1[(256 + d) * 256 + j];
            g_emb[u * HH + j] = s;
        }
        if (tid == 1536 || tid == 1537) {
            int u = tid - 1536;
            const float* b2 = u ? bb2 : bc2;
            float s = bl[0];
            for (int d = 0; d < 128; d++) s += b2[d] * Wl[d];
            g_pbias[u] = s;
        }
    } else {
        int tid2 = (b - 64) * 512 + t;          // 0..32767
        {   // WfT: 512 rows (out cols) x 256 k; 32768 float4 slots
            int o = tid2 >> 6, kq = (tid2 & 63) * 4;
            float4 v;
            if (o < 256)
                v = make_float4(Wc1[(kq+0)*256 + o], Wc1[(kq+1)*256 + o],
                                Wc1[(kq+2)*256 + o], Wc1[(kq+3)*256 + o]);
            else {
                int o2 = o - 256;
                v = make_float4(Wb1[(kq+0)*256 + o2], Wb1[(kq+1)*256 + o2],
                                Wb1[(kq+2)*256 + o2], Wb1[(kq+3)*256 + o2]);
            }
            *((float4*)&g_WfT[(size_t)o * 256 + kq]) = v;
        }
        if (tid2 < 8192) {   // Wc2T: 128 x 256 = 8192 float4
            int o = tid2 >> 6, kq = (tid2 & 63) * 4;
            *((float4*)&g_Wc2T[(size_t)o * 256 + kq]) =
                make_float4(Wc2[(kq+0)*128 + o], Wc2[(kq+1)*128 + o],
                            Wc2[(kq+2)*128 + o], Wc2[(kq+3)*128 + o]);
        } else if (tid2 < 16384) {
            int td = tid2 - 8192;
            int o = td >> 6, kq = (td & 63) * 4;
            *((float4*)&g_Wb2T[(size_t)o * 256 + kq]) =
                make_float4(Wb2[(kq+0)*128 + o], Wb2[(kq+1)*128 + o],
                            Wb2[(kq+2)*128 + o], Wb2[(kq+3)*128 + o]);
        }
    }
}

extern "C" void kernel_launch(void* const* d_in, const int* in_sizes, int n_in,
                              void* d_out, int out_size)
{
    const int*   info_bits = (const int*)  d_in[0];
    const float* r_in      = (const float*)d_in[1];
    const int*   info_set  = (const int*)  d_in[2];
    const float* E_obs     = (const float*)d_in[3];
    const float* E_lab     = (const float*)d_in[4];
    const float* Wc1 = (const float*)d_in[5];
    const float* bc1 = (const float*)d_in[6];
    const float* Wc2 = (const float*)d_in[7];
    const float* bc2 = (const float*)d_in[8];
    const float* Wb1 = (const float*)d_in[9];
    const float* bb1 = (const float*)d_in[10];
    const float* Wb2 = (const float*)d_in[11];
    const float* bb2 = (const float*)d_in[12];
    const float* Wl  = (const float*)d_in[13];
    const float* bl  = (const float*)d_in[14];
    float* out = (float*)d_out;

    // smem: sa 32K + hs 32K + arena 64K + nbp/nx ~1.1K
    const int smem = (8192 + 8192 + 16384 + 256 + 8) * 4;
    cudaFuncSetAttribute(sc_main, cudaFuncAttributeMaxDynamicSharedMemorySize, smem);

    sc_init<<<BATCH, 512>>>(info_bits, r_in, info_set, E_obs, out,
                            Wc1, bc1, Wb1, bb1, E_lab, Wc2, bc2, Wb2, bb2, Wl, bl);
    sc_main<<<BATCH, THREADS, smem>>>(r_in, Wc2, bc2, Wb2, bb2, out);
}

// round 17
// speedup vs baseline: 2.5407x; 2.5407x over previous
#include <cuda_runtime.h>
#include <math.h>

#define BATCH   128
#define DD      128
#define HH      256
#define NBLK_C  256
#define THREADS 1024
#define SEC     (BATCH*NBLK_C)

typedef unsigned long long u64;

// ---- device scratch ----
__device__ __align__(16) float g_E[BATCH * 511 * DD];
__device__ __align__(16) float g_BP[BATCH * 255 * HH];
__device__ int   g_X[BATCH * 511];
__device__ int   g_U1H[BATCH * 256];
__device__ int   g_fenc[BATCH * NBLK_C];
__device__ __align__(16) float g_Wf[256 * 512];   // [Wc1 | Wb1-top] col-fused
__device__ __align__(16) float g_bf[512];         // [bc1 | bb1]
__device__ __align__(16) float g_emb[2 * HH];     // E_lab[u] @ Wb1[256:384,:]
__device__ __align__(16) float g_w2l[512];        // [Wc2@Wl | Wb2@Wl]
__device__ float g_pbias[2];

// ---- f32x2 helpers ----
__device__ __forceinline__ void fma2(u64& acc, u64 a, u64 b) {
    asm("fma.rn.f32x2 %0, %1, %2, %0;" : "+l"(acc) : "l"(a), "l"(b));
}
__device__ __forceinline__ u64 pk2(float x, float y) {
    u64 r; asm("mov.b64 %0, {%1, %2};" : "=l"(r) : "f"(x), "f"(y)); return r;
}
__device__ __forceinline__ float2 upk(u64 v) {
    float2 r; asm("mov.b64 {%0, %1}, %2;" : "=f"(r.x), "=f"(r.y) : "l"(v)); return r;
}

struct Ctx {
    float* Eb; float* BPb; int* Xb; int* U1Hb;
    float* sa;     // 32 KB
    float* hs;     // 32 KB
    float* arena;  // 64 KB
    float* nh; float* nbp; int* nx;
    const float* Wc2; const float* bc2;
    const float* Wb2; const float* bb2;
    const float* r_in;
    float* u_out; float* p_out;
    int b;
};

// ============ L1 fused GEMM: [R x 256] @ [256 x 512] (R12) ============
template<int R, int RG, int KP>
__device__ void l1_gemm(Ctx& c, const float* __restrict__ Ein, float* __restrict__ bp_out)
{
    const int t = threadIdx.x;
    constexpr int NR = R / RG;
    constexpr int KL = 256 / KP;
    {
        const float4* src = (const float4*)Ein;
        float4* dst = (float4*)c.sa;
        for (int i = t; i < R * 64; i += THREADS) dst[i] = src[i];
    }
    __syncthreads();
    const int colq = t & 127;
    const int s  = t >> 7;
    const int rg = s % RG;
    const int kp = s / RG;
    const int k0 = kp * KL;
    const int r0 = rg * NR;
    u64 acc[NR][2];
    #pragma unroll
    for (int j = 0; j < NR; j++) { acc[j][0] = 0ull; acc[j][1] = 0ull; }
    const ulonglong2* W = (const ulonglong2*)g_Wf + colq;
    #pragma unroll 2
    for (int k = k0; k < k0 + KL; k += 2) {
        ulonglong2 w0 = __ldg(W + (size_t)k * 128);
        ulonglong2 w1 = __ldg(W + (size_t)(k + 1) * 128);
        #pragma unroll
        for (int j = 0; j < NR; j++) {
            float2 a = *((const float2*)&c.sa[(r0 + j) * 256 + k]);
            u64 ax = pk2(a.x, a.x), ay = pk2(a.y, a.y);
            fma2(acc[j][0], ax, w0.x); fma2(acc[j][1], ax, w0.y);
            fma2(acc[j][0], ay, w1.x); fma2(acc[j][1], ay, w1.y);
        }
    }
    if constexpr (KP == 1) {
        const int col = colq * 4;
        float4 bias = *((const float4*)&g_bf[col]);
        #pragma unroll
        for (int j = 0; j < NR; j++) {
            int row = r0 + j;
            float2 v0 = upk(acc[j][0]); float2 v1 = upk(acc[j][1]);
            float o0 = v0.x + bias.x, o1 = v0.y + bias.y;
            float o2 = v1.x + bias.z, o3 = v1.y + bias.w;
            if (col < 256)
                *((float4*)&c.hs[row * 256 + col]) =
                    make_float4(fmaxf(o0,0.f), fmaxf(o1,0.f), fmaxf(o2,0.f), fmaxf(o3,0.f));
            else
                *((float4*)&bp_out[row * HH + (col - 256)]) = make_float4(o0, o1, o2, o3);
        }
        __syncthreads();
    } else {
        ulonglong2* ar = (ulonglong2*)c.arena;
        #pragma unroll
        for (int j = 0; j < NR; j++) {
            ulonglong2 v; v.x = acc[j][0]; v.y = acc[j][1];
            ar[(s * NR + j) * 128 + colq] = v;
        }
        __syncthreads();
        for (int o = t; o < R * 128; o += THREADS) {
            int row = o >> 7, cq = o & 127;
            int jr = row % NR, rr = row / NR;
            float sx = 0.f, sy = 0.f, sz = 0.f, sw = 0.f;
            #pragma unroll
            for (int q = 0; q < KP; q++) {
                ulonglong2 v = ar[((q * RG + rr) * NR + jr) * 128 + cq];
                float2 p0 = upk(v.x), p1 = upk(v.y);
                sx += p0.x; sy += p0.y; sz += p1.x; sw += p1.y;
            }
            int col = cq * 4;
            float4 bias = *((const float4*)&g_bf[col]);
            sx += bias.x; sy += bias.y; sz += bias.z; sw += bias.w;
            if (col < 256)
                *((float4*)&c.hs[row * 256 + col]) =
                    make_float4(fmaxf(sx,0.f), fmaxf(sy,0.f), fmaxf(sz,0.f), fmaxf(sw,0.f));
            else
                *((float4*)&bp_out[row * HH + (col - 256)]) = make_float4(sx, sy, sz, sw);
        }
        __syncthreads();
    }
}

// ============ L2 GEMM: [R x 256] @ [256 x 128] + b2 (R12) ============
template<int R, int RG, int KP>
__device__ void l2_gemm(Ctx& c, const float* __restrict__ W2,
                        const float* __restrict__ b2, float* __restrict__ Eout)
{
    const int t = threadIdx.x;
    constexpr int NR = R / RG;
    constexpr int KL = 256 / KP;
    const int colq = t & 31;
    const int s  = t >> 5;
    const int rg = s % RG;
    const int kp = s / RG;
    const int k0 = kp * KL;
    const int r0 = rg * NR;
    u64 acc[NR][2];
    #pragma unroll
    for (int j = 0; j < NR; j++) { acc[j][0] = 0ull; acc[j][1] = 0ull; }
    const ulonglong2* W = (const ulonglong2*)W2 + colq;
    #pragma unroll 2
    for (int k = k0; k < k0 + KL; k += 2) {
        ulonglong2 w0 = __ldg(W + (size_t)k * 32);
        ulonglong2 w1 = __ldg(W + (size_t)(k + 1) * 32);
        #pragma unroll
        for (int j = 0; j < NR; j++) {
            float2 a = *((const float2*)&c.hs[(r0 + j) * 256 + k]);
            u64 ax = pk2(a.x, a.x), ay = pk2(a.y, a.y);
            fma2(acc[j][0], ax, w0.x); fma2(acc[j][1], ax, w0.y);
            fma2(acc[j][0], ay, w1.x); fma2(acc[j][1], ay, w1.y);
        }
    }
    ulonglong2* ar = (ulonglong2*)c.arena;
    #pragma unroll
    for (int j = 0; j < NR; j++) {
        ulonglong2 v; v.x = acc[j][0]; v.y = acc[j][1];
        ar[(s * NR + j) * 32 + colq] = v;
    }
    __syncthreads();
    for (int o = t; o < R * 32; o += THREADS) {
        int row = o >> 5, cq = o & 31;
        int jr = row % NR, rr = row / NR;
        float sx = 0.f, sy = 0.f, sz = 0.f, sw = 0.f;
        #pragma unroll
        for (int q = 0; q < KP; q++) {
            ulonglong2 v = ar[((q * RG + rr) * NR + jr) * 32 + cq];
            float2 p0 = upk(v.x), p1 = upk(v.y);
            sx += p0.x; sy += p0.y; sz += p1.x; sw += p1.y;
        }
        int col = cq * 4;
        float4 bb = *((const float4*)&b2[col]);
        *((float4*)&Eout[row * 128 + col]) =
            make_float4(sx + bb.x, sy + bb.y, sz + bb.z, sw + bb.w);
    }
    __syncthreads();
}

// ============ UNIFORM check (initial descent): all rows identical ============
// Compute ONE row through L1+L2 and broadcast bp / E-out to all rows.
__device__ void check_u(Ctx& c, int l)
{
    const int t = threadIdx.x;
    const int half = 1 << (l - 1);
    const float* Ein = c.Eb + ((1 << l) - 1) * DD;   // row 0 (256 floats)
    float* Eout = c.Eb + (half - 1) * DD;
    float* BPl  = c.BPb + (half - 1) * HH;
    // L1: 1 row, full Wf stream (KP=8, node1 pattern)
    {
        const int colq = t & 127;
        const int kp   = t >> 7;
        const int k0   = kp * 32;
        u64 acc0 = 0ull, acc1 = 0ull;
        const ulonglong2* W = (const ulonglong2*)g_Wf + colq;
        #pragma unroll
        for (int kb = 0; kb < 32; kb += 4) {
            float4 a4 = __ldg((const float4*)&Ein[k0 + kb]);
            ulonglong2 w; u64 a;
            w = __ldg(W + (size_t)(k0 + kb + 0) * 128); a = pk2(a4.x, a4.x); fma2(acc0, a, w.x); fma2(acc1, a, w.y);
            w = __ldg(W + (size_t)(k0 + kb + 1) * 128); a = pk2(a4.y, a4.y); fma2(acc0, a, w.x); fma2(acc1, a, w.y);
            w = __ldg(W + (size_t)(k0 + kb + 2) * 128); a = pk2(a4.z, a4.z); fma2(acc0, a, w.x); fma2(acc1, a, w.y);
            w = __ldg(W + (size_t)(k0 + kb + 3) * 128); a = pk2(a4.w, a4.w); fma2(acc0, a, w.x); fma2(acc1, a, w.y);
        }
        float2 v0 = upk(acc0), v1 = upk(acc1);
        ((float4*)c.arena)[kp * 128 + colq] = make_float4(v0.x, v0.y, v1.x, v1.y);
    }
    __syncthreads();
    if (t < 512) {
        float v = g_bf[t];
        #pragma unroll
        for (int q = 0; q < 8; q++) v += c.arena[q * 512 + t];
        if (t < 256) c.hs[t] = fmaxf(v, 0.f);
        else c.nbp[t - 256] = v;
    }
    __syncthreads();
    // broadcast bp to all rows + L2 single-row stream (KP=32)
    for (int idx = t; idx < half * 256; idx += THREADS) {
        int row = idx >> 8, k = idx & 255;
        BPl[row * HH + k] = c.nbp[k];
    }
    {
        const int colq = t & 31;
        const int kp   = t >> 5;
        const int k0   = kp * 8;
        u64 a0 = 0ull, a1 = 0ull;
        const ulonglong2* W = (const ulonglong2*)c.Wc2 + colq;
        #pragma unroll
        for (int kk = 0; kk < 8; kk++) {
            int k = k0 + kk;
            float h = c.hs[k];
            u64 hp = pk2(h, h);
            ulonglong2 w = __ldg(W + (size_t)k * 32);
            fma2(a0, hp, w.x); fma2(a1, hp, w.y);
        }
        float2 v0 = upk(a0), v1 = upk(a1);
        ((float4*)c.arena)[kp * 32 + colq] = make_float4(v0.x, v0.y, v1.x, v1.y);
    }
    __syncthreads();
    if (t < 128) {
        float v = __ldg(&c.bc2[t]);
        #pragma unroll 8
        for (int q = 0; q < 32; q++) v += c.arena[q * 128 + t];
        c.nh[t] = v;
    }
    __syncthreads();
    for (int idx = t; idx < half * 128; idx += THREADS) {
        int row = idx >> 7, k = idx & 127;
        Eout[row * 128 + k] = c.nh[k];
    }
    __syncthreads();
}

__device__ void check_stage(Ctx& c, int l)
{
    const int half = 1 << (l - 1);
    const float* Ein = c.Eb + ((1 << l) - 1) * DD;
    float* Eout = c.Eb + (half - 1) * DD;
    float* BPl  = c.BPb + (half - 1) * HH;
    if (half == 2)       { l1_gemm<2,1,8>(c, Ein, BPl);   l2_gemm<2,1,32>(c, c.Wc2, c.bc2, Eout); }
    else if (half == 4)  { l1_gemm<4,1,8>(c, Ein, BPl);   l2_gemm<4,1,32>(c, c.Wc2, c.bc2, Eout); }
    else if (half == 8)  { l1_gemm<8,2,4>(c, Ein, BPl);   l2_gemm<8,2,16>(c, c.Wc2, c.bc2, Eout); }
    else if (half == 16) { l1_gemm<16,4,2>(c, Ein, BPl);  l2_gemm<16,4,8>(c, c.Wc2, c.bc2, Eout); }
    else {
        for (int done = 0; done < half; done += 32) {
            l1_gemm<32,8,1>(c, Ein + done * 256, BPl + done * HH);
            l2_gemm<32,8,4>(c, c.Wc2, c.bc2, Eout + done * DD);
        }
    }
}

__device__ void bit_hidden(Ctx& c, const float* BPl, const int* u1h, int done, int rbc)
{
    for (int idx = threadIdx.x; idx < rbc * 256; idx += THREADS) {
        int row = idx >> 8, k = idx & 255;
        int u = u1h[done + row];
        c.hs[idx] = fmaxf(BPl[(done + row) * HH + k] + g_emb[u * HH + k], 0.f);
    }
    __syncthreads();
}

__device__ void bit_stage(Ctx& c, int l)
{
    const int half = 1 << (l - 1);
    const int base = half - 1;
    float* Eout = c.Eb + base * DD;
    const float* BPl = c.BPb + base * HH;
    int* u1h = c.U1Hb + base;
    int* Xlm = c.Xb + base;
    __syncthreads();
    for (int i = threadIdx.x; i < half; i += THREADS) u1h[i] = Xlm[i];
    __syncthreads();
    if (half == 2)       { bit_hidden(c, BPl, u1h, 0, 2);  l2_gemm<2,1,32>(c, c.Wb2, c.bb2, Eout); }
    else if (half == 4)  { bit_hidden(c, BPl, u1h, 0, 4);  l2_gemm<4,1,32>(c, c.Wb2, c.bb2, Eout); }
    else if (half == 8)  { bit_hidden(c, BPl, u1h, 0, 8);  l2_gemm<8,2,16>(c, c.Wb2, c.bb2, Eout); }
    else if (half == 16) { bit_hidden(c, BPl, u1h, 0, 16); l2_gemm<16,4,8>(c, c.Wb2, c.bb2, Eout); }
    else {
        for (int done = 0; done < half; done += 32) {
            bit_hidden(c, BPl, u1h, done, 32);
            l2_gemm<32,8,4>(c, c.Wb2, c.bb2, Eout + done * DD);
        }
    }
}

__device__ __forceinline__ void combine_stage(Ctx& c, int l)
{
    int half = 1 << (l - 1);
    int* u1h = c.U1Hb + (half - 1);
    int* Xlm = c.Xb + (half - 1);
    int* Xl  = c.Xb + ((1 << l) - 1);
    __syncthreads();
    for (int i = threadIdx.x; i < half; i += THREADS) {
        int u2 = Xlm[i];
        Xl[2 * i]     = u1h[i] ^ u2;
        Xl[2 * i + 1] = u2;
    }
    __syncthreads();
}

// Fused level-1 node (R12)
__device__ void node1(Ctx& c, int n)
{
    const int t = threadIdx.x;
    const float* Ein = c.Eb + DD;
    const int colq = t & 127;
    const int kp   = t >> 7;
    const int k0   = kp * 32;
    u64 acc0 = 0ull, acc1 = 0ull;
    const ulonglong2* W = (const ulonglong2*)g_Wf + colq;
    #pragma unroll
    for (int kb = 0; kb < 32; kb += 4) {
        float4 a4 = __ldg((const float4*)&Ein[k0 + kb]);
        ulonglong2 w; u64 a;
        w = __ldg(W + (size_t)(k0 + kb + 0) * 128); a = pk2(a4.x, a4.x); fma2(acc0, a, w.x); fma2(acc1, a, w.y);
        w = __ldg(W + (size_t)(k0 + kb + 1) * 128); a = pk2(a4.y, a4.y); fma2(acc0, a, w.x); fma2(acc1, a, w.y);
        w = __ldg(W + (size_t)(k0 + kb + 2) * 128); a = pk2(a4.z, a4.z); fma2(acc0, a, w.x); fma2(acc1, a, w.y);
        w = __ldg(W + (size_t)(k0 + kb + 3) * 128); a = pk2(a4.w, a4.w); fma2(acc0, a, w.x); fma2(acc1, a, w.y);
    }
    float2 v0 = upk(acc0), v1 = upk(acc1);
    ((float4*)c.arena)[kp * 128 + colq] = make_float4(v0.x, v0.y, v1.x, v1.y);
    __syncthreads();
    if (t < 512) {
        float v = g_bf[t];
        #pragma unroll
        for (int q = 0; q < 8; q++) v += c.arena[q * 512 + t];
        if (t < 256) c.nh[t] = fmaxf(v, 0.f);
        else c.nbp[t - 256] = v;
    }
    __syncthreads();
    if (t < 32) {
        float s = 0.f;
        #pragma unroll
        for (int j = 0; j < 8; j++) s = fmaf(c.nh[t + 32 * j], g_w2l[t + 32 * j], s);
        #pragma unroll
        for (int o = 16; o > 0; o >>= 1) s += __shfl_xor_sync(0xffffffffu, s, o);
        if (t == 0) {
            float p = 1.f / (1.f + expf(-(s + g_pbias[0])));
            int leaf = 2 * n;
            float rv = __ldg(&c.r_in[c.b * NBLK_C + leaf]);
            int f  = g_fenc[c.b * NBLK_C + leaf];
            int hd = (rv > p) ? 1 : 0;
            int x  = ((f == 2) || (fabsf(p - 0.5f) > 0.25f)) ? hd : f;
            *c.nx = x;
            c.u_out[c.b * NBLK_C + leaf] = (float)x;
            c.p_out[c.b * NBLK_C + leaf] = p;
        }
    }
    __syncthreads();
    int xL = *c.nx;
    if (t < 256)
        c.arena[t] = fmaxf(c.nbp[t] + g_emb[xL * HH + t], 0.f) * g_w2l[256 + t];
    __syncthreads();
    if (t < 32) {
        float s = 0.f;
        #pragma unroll
        for (int j = 0; j < 8; j++) s += c.arena[t + 32 * j];
        #pragma unroll
        for (int o = 16; o > 0; o >>= 1) s += __shfl_xor_sync(0xffffffffu, s, o);
        if (t == 0) {
            float p = 1.f / (1.f + expf(-(s + g_pbias[1])));
            int leaf = 2 * n + 1;
            float rv = __ldg(&c.r_in[c.b * NBLK_C + leaf]);
            int f  = g_fenc[c.b * NBLK_C + leaf];
            int hd = (rv > p) ? 1 : 0;
            int xR = ((f == 2) || (fabsf(p - 0.5f) > 0.25f)) ? hd : f;
            c.u_out[c.b * NBLK_C + leaf] = (float)xR;
            c.p_out[c.b * NBLK_C + leaf] = p;
            c.Xb[1] = xL ^ xR;
            c.Xb[2] = xR;
        }
    }
    __syncthreads();
}

__global__ void __launch_bounds__(THREADS, 1)
sc_main(const float* r_in,
        const float* Wc2, const float* bc2,
        const float* Wb2, const float* bb2,
        float* out)
{
    extern __shared__ __align__(16) char smraw[];
    Ctx c;
    c.sa    = (float*)smraw;           // 32 KB
    c.hs    = c.sa + 8192;             // 32 KB
    c.arena = c.hs + 8192;             // 64 KB
    c.nh    = c.arena + 16384;
    c.nbp   = c.nh + 256;
    c.nx    = (int*)(c.nbp + 256);
    c.b = blockIdx.x;
    c.Eb   = g_E   + (size_t)c.b * 511 * DD;
    c.BPb  = g_BP  + (size_t)c.b * 255 * HH;
    c.Xb   = g_X   + c.b * 511;
    c.U1Hb = g_U1H + c.b * 256;
    c.Wc2 = Wc2; c.bc2 = bc2; c.Wb2 = Wb2; c.bb2 = bb2;
    c.r_in  = r_in;
    c.u_out = out + 2 * SEC;
    c.p_out = out + 3 * SEC;

    // initial descent: all rows identical -> uniform single-row checks
    for (int l = 8; l >= 2; l--) check_u(c, l);
    for (int n = 0; n < 128; n++) {
        node1(c, n);
        if (n == 127) break;
        int l = 2;
        while ((n >> (l - 2)) & 1) { combine_stage(c, l); l++; }
        bit_stage(c, l);
        for (int ld = l - 1; ld >= 2; ld--) check_stage(c, ld);
    }
    for (int l = 2; l <= 8; l++) combine_stage(c, l);

    int* X8 = c.Xb + 255;
    for (int i = threadIdx.x; i < NBLK_C; i += THREADS)
        out[c.b * NBLK_C + i] = (float)X8[i];
}

// ---- merged init (E8 init now only rows 0-1 per batch) ----
__global__ void sc_init(const int* info_bits, const float* r_in, const int* info_set,
                        const float* E_obs, float* out,
                        const float* Wc1, const float* bc1,
                        const float* Wb1, const float* bb1,
                        const float* E_lab,
                        const float* Wc2, const float* bc2,
                        const float* Wb2, const float* bb2,
                        const float* Wl, const float* bl)
{
    int b = blockIdx.x, t = threadIdx.x;
    for (int j = t; j < NBLK_C; j += blockDim.x) {
        g_fenc[b * NBLK_C + j] = 2;
        out[1 * SEC + b * NBLK_C + j] = 1.0f;
        out[4 * SEC + b * NBLK_C + j] = r_in[b * NBLK_C + j];
    }
    __syncthreads();
    for (int k = t; k < 128; k += blockDim.x) {
        int pos = info_set[k];
        g_fenc[b * NBLK_C + pos] = info_bits[b * 128 + k];
        out[1 * SEC + b * NBLK_C + pos] = 2.0f;
    }
    // E level-8: only rows 0,1 are read (uniform initial check)
    for (int idx = t; idx < 256; idx += blockDim.x) {
        g_E[(size_t)b * 511 * DD + 255 * DD + idx] = E_obs[2 * DD + (idx & 127)];
    }
    if (b < 64) {
        int tid = b * 512 + t;
        {
            int k = tid >> 7, c4 = (tid & 127) * 4;
            float4 v;
            if (c4 < 256) v = *((const float4*)&Wc1[k * 256 + c4]);
            else          v = *((const float4*)&Wb1[k * 256 + (c4 - 256)]);
            *((float4*)&g_Wf[k * 512 + c4]) = v;
        }
        if (tid < 512) g_bf[tid] = (tid < 256) ? bc1[tid] : bb1[tid - 256];
        if (tid >= 512 && tid < 1024) {
            int cidx = tid - 512;
            const float* W2 = (cidx < 256) ? Wc2 : Wb2;
            int k = cidx & 255;
            float s = 0.f;
            for (int d = 0; d < 128; d++) s += W2[k * 128 + d] * Wl[d];
            g_w2l[cidx] = s;
        }
        if (tid >= 1024 && tid < 1536) {
            int cidx = tid - 1024; int u = cidx >> 8, j = cidx & 255;
            float s = 0.f;
            for (int d = 0; d < 128; d++) s += E_lab[u * 128 + d] * Wb1[(256 + d) * 256 + j];
            g_emb[u * HH + j] = s;
        }
        if (tid == 1536 || tid == 1537) {
            int u = tid - 1536;
            const float* b2 = u ? bb2 : bc2;
            float s = bl[0];
            for (int d = 0; d < 128; d++) s += b2[d] * Wl[d];
            g_pbias[u] = s;
        }
    }
}

extern "C" void kernel_launch(void* const* d_in, const int* in_sizes, int n_in,
                              void* d_out, int out_size)
{
    const int*   info_bits = (const int*)  d_in[0];
    const float* r_in      = (const float*)d_in[1];
    const int*   info_set  = (const int*)  d_in[2];
    const float* E_obs     = (const float*)d_in[3];
    const float* E_lab     = (const float*)d_in[4];
    const float* Wc1 = (const float*)d_in[5];
    const float* bc1 = (const float*)d_in[6];
    const float* Wc2 = (const float*)d_in[7];
    const float* bc2 = (const float*)d_in[8];
    const float* Wb1 = (const float*)d_in[9];
    const float* bb1 = (const float*)d_in[10];
    const float* Wb2 = (const float*)d_in[11];
    const float* bb2 = (const float*)d_in[12];
    const float* Wl  = (const float*)d_in[13];
    const float* bl  = (const float*)d_in[14];
    float* out = (float*)d_out;

    const int smem = (8192 + 8192 + 16384 + 256 + 256 + 8) * 4;
    cudaFuncSetAttribute(sc_main, cudaFuncAttributeMaxDynamicSharedMemorySize, smem);

    sc_init<<<BATCH, 512>>>(info_bits, r_in, info_set, E_obs, out,
                            Wc1, bc1, Wb1, bb1, E_lab, Wc2, bc2, Wb2, bb2, Wl, bl);
    sc_main<<<BATCH, THREADS, smem>>>(r_in, Wc2, bc2, Wb2, bb2, out);
}